// round 13
// baseline (speedup 1.0000x reference)
#include <cuda_runtime.h>

#define N_NODES 100000
#define N_EDGES 600000
#define HIDDEN  128
#define HID4    (HIDDEN / 4)
#define BN_EPS  1e-5f

typedef unsigned long long u64;

// Scratch (device globals: no allocation allowed in kernel_launch).
__device__ float4 g_h4[(size_t)N_NODES * HID4];    // relu(x) @ W
__device__ int    g_deg[N_NODES];
__device__ float  g_dinv[N_NODES];
__device__ int    g_off[N_NODES];                  // CSR segment starts (unordered)
__device__ int    g_cursor[N_NODES];               // fill cursors
__device__ int    g_total;                         // bump-allocator counter
__device__ int2   g_entry[N_EDGES];                // (src row, weight bits)
__device__ double g_sum[HIDDEN];
__device__ double g_sumsq[HIDDEN];
__device__ float4 g_scale4[HID4];
__device__ float4 g_shift4[HID4];

// Packed 2-lane fp32 FMA (sm_100+ PTX; ptxas never auto-emits FFMA2 from C++).
__device__ __forceinline__ u64 ffma2(u64 a, u64 b, u64 c)
{
    u64 d;
    asm("fma.rn.f32x2 %0, %1, %2, %3;" : "=l"(d) : "l"(a), "l"(b), "l"(c));
    return d;
}
__device__ __forceinline__ u64 dup2(float x)
{
    u64 d;
    asm("mov.b64 %0, {%1, %1};" : "=l"(d) : "f"(x));
    return d;
}

// ---------------------------------------------------------------------------
// Init: deg=1 (self loop), zero BN accumulators + bump counter. out needs NO
// zeroing: the gather-aggregation writes every row completely.
// ---------------------------------------------------------------------------
__global__ void k_init()
{
    int i = blockIdx.x * blockDim.x + threadIdx.x;
    int stride = gridDim.x * blockDim.x;
    for (int idx = i; idx < N_NODES; idx += stride) g_deg[idx] = 1;
    if (i < HIDDEN) { g_sum[i] = 0.0; g_sumsq[i] = 0.0; }
    if (i == 0) g_total = 0;
}

// ---------------------------------------------------------------------------
// Degree of target nodes (col), on top of the self-loop baseline of 1.
// edge_index is int32 (JAX default config downcasts int64 -> int32).
// ---------------------------------------------------------------------------
__global__ void k_deg(const int* __restrict__ col, int E)
{
    int i = blockIdx.x * blockDim.x + threadIdx.x;
    if (i < E) {
        int c = col[i];
        if ((unsigned)c < N_NODES) atomicAdd(&g_deg[c], 1);
    }
}

// ---------------------------------------------------------------------------
// Fused dinv + CSR segment allocation (no prefix scan needed: segments only
// have to be contiguous per node). Uniform-address atomicAdd is warp-
// aggregated by ptxas (REDUX.SUM + elect + one L2 atomic per warp).
// ---------------------------------------------------------------------------
__global__ void k_prep()
{
    int i = blockIdx.x * blockDim.x + threadIdx.x;
    if (i < N_NODES) {
        int dg = g_deg[i];
        g_dinv[i] = rsqrtf((float)dg);
        int pos = atomicAdd(&g_total, dg - 1);
        g_off[i]    = pos;
        g_cursor[i] = pos;
    }
}

// ---------------------------------------------------------------------------
// Fill CSR entries: per edge, (src row, dinv[r]*dinv[c]) bucketed by target.
// ---------------------------------------------------------------------------
__global__ void k_fill(const int* __restrict__ ei, int E)
{
    int i = blockIdx.x * blockDim.x + threadIdx.x;
    if (i < E) {
        int r = ei[i];
        int c = ei[E + i];
        if ((unsigned)c >= N_NODES) return;            // matches k_deg guard
        float w = 0.f;
        if ((unsigned)r < N_NODES) w = g_dinv[r] * g_dinv[c];
        else r = 0;                                    // defensive, w=0
        int pos = atomicAdd(&g_cursor[c], 1);
        g_entry[pos] = make_int2(r, __float_as_int(w));
    }
}

// ---------------------------------------------------------------------------
// h = relu(x) @ W.   Register-tiled SGEMM with packed f32x2 FMA.
// Block: 128 rows x 128 cols, 256 threads, 8x8 micro-tile per thread held as
// 32 packed f32x2 accumulators. Per k-step: 4 LDS.128 -> 32 FFMA2 (= 64 MACs).
// ---------------------------------------------------------------------------
#define BLOCK_M 128
#define KC      32

__global__ void __launch_bounds__(256) k_gemm(const float* __restrict__ x,
                                              const float* __restrict__ W)
{
    __shared__ __align__(16) float Ws[KC][HIDDEN];     // 16 KB  [k][col]
    __shared__ __align__(16) float Xs[KC][BLOCK_M];    // 16 KB  [k][row]

    const int tid = threadIdx.x;
    const int tx  = tid & 15;            // col group: cols tx*8 .. tx*8+7
    const int ty  = tid >> 4;            // row group: rows ty*8 .. ty*8+7
    const int rowBase = blockIdx.x * BLOCK_M;

    u64 acc2[8][4];                      // [row][col-pair], packed f32x2
    #pragma unroll
    for (int r = 0; r < 8; r++)
        #pragma unroll
        for (int q = 0; q < 4; q++) acc2[r][q] = 0ull;

    for (int k0 = 0; k0 < HIDDEN; k0 += KC) {
        __syncthreads();                 // previous chunk fully consumed

        // W chunk: rows k0..k0+31 are 4096 contiguous floats. 4 float4/thread.
        {
            const float4* w4  = (const float4*)(W + k0 * HIDDEN);
            float4*       ws4 = (float4*)&Ws[0][0];
            #pragma unroll
            for (int i = 0; i < 4; i++)
                ws4[tid + 256 * i] = w4[tid + 256 * i];
        }
        // x chunk, transposed + ReLU -> Xs[k][row].
        {
            #pragma unroll
            for (int i = 0; i < 4; i++) {
                int f   = tid + 256 * i;
                int row = f >> 3;                   // 0..127
                int q   = f & 7;                    // float4 index within 32 cols
                int grow = rowBase + row;
                float4 v = make_float4(0.f, 0.f, 0.f, 0.f);
                if (grow < N_NODES) {
                    v = *(const float4*)(x + (size_t)grow * HIDDEN + k0 + 4 * q);
                    v.x = fmaxf(v.x, 0.f); v.y = fmaxf(v.y, 0.f);
                    v.z = fmaxf(v.z, 0.f); v.w = fmaxf(v.w, 0.f);
                }
                Xs[4 * q + 0][row] = v.x;
                Xs[4 * q + 1][row] = v.y;
                Xs[4 * q + 2][row] = v.z;
                Xs[4 * q + 3][row] = v.w;
            }
        }
        __syncthreads();

        #pragma unroll
        for (int kk = 0; kk < KC; kk++) {
            float  xr[8];
            float4 wq0, wq1;
            *(float4*)&xr[0] = *(const float4*)&Xs[kk][ty * 8];
            *(float4*)&xr[4] = *(const float4*)&Xs[kk][ty * 8 + 4];
            wq0 = *(const float4*)&Ws[kk][tx * 8];
            wq1 = *(const float4*)&Ws[kk][tx * 8 + 4];
            u64 w2[4];
            w2[0] = ((const u64*)&wq0)[0];
            w2[1] = ((const u64*)&wq0)[1];
            w2[2] = ((const u64*)&wq1)[0];
            w2[3] = ((const u64*)&wq1)[1];
            #pragma unroll
            for (int r = 0; r < 8; r++) {
                u64 x2 = dup2(xr[r]);
                #pragma unroll
                for (int q = 0; q < 4; q++)
                    acc2[r][q] = ffma2(x2, w2[q], acc2[r][q]);
            }
        }
    }

    // Epilogue: packed pairs are already column-ordered -> two STG.128/row.
    float* gh = (float*)g_h4;
    #pragma unroll
    for (int r = 0; r < 8; r++) {
        int row = rowBase + ty * 8 + r;
        if (row < N_NODES) {
            float* dst = gh + (size_t)row * HIDDEN + tx * 8;
            *(float4*)dst       = *(float4*)&acc2[r][0];
            *(float4*)(dst + 4) = *(float4*)&acc2[r][2];
        }
    }
}

// ---------------------------------------------------------------------------
// Gather aggregation + fused BN statistics. One warp per target node.
// out[c] = dinv[c]^2 * h[c] + sum_in-edges w * h[r];  full row in registers.
// Edge loop unrolled x4 with batched entry prefetch: 4 independent entry
// loads, then 4 independent row gathers -> ~2x the in-flight loads of the
// previous x2 version (agg is latency-bound at ~40% of the L2 BW cap).
// Per-thread float partial sums -> block shared doubles -> global doubles.
// ---------------------------------------------------------------------------
__global__ void __launch_bounds__(256) k_agg(float* __restrict__ out)
{
    __shared__ double bsum[HIDDEN];
    __shared__ double bsq[HIDDEN];

    const int tid = threadIdx.x;
    if (tid < HIDDEN) { bsum[tid] = 0.0; bsq[tid] = 0.0; }
    __syncthreads();

    const int lane   = tid & 31;
    const int warp   = (blockIdx.x * blockDim.x + tid) >> 5;
    const int nwarps = (gridDim.x * blockDim.x) >> 5;

    float4 ts = make_float4(0.f, 0.f, 0.f, 0.f);     // per-thread col sums
    float4 tq = make_float4(0.f, 0.f, 0.f, 0.f);     // per-thread col sumsq

    for (int c = warp; c < N_NODES; c += nwarps) {
        float d = g_dinv[c];
        float wself = d * d;
        float4 v = g_h4[(size_t)c * HID4 + lane];
        float4 acc = make_float4(v.x * wself, v.y * wself, v.z * wself, v.w * wself);

        const int beg = g_off[c];
        const int end = beg + g_deg[c] - 1;
        int e = beg;
        for (; e + 4 <= end; e += 4) {
            // 4 independent entry loads, then 4 independent row gathers.
            int2 en0 = g_entry[e];
            int2 en1 = g_entry[e + 1];
            int2 en2 = g_entry[e + 2];
            int2 en3 = g_entry[e + 3];
            float4 h0 = g_h4[(size_t)en0.x * HID4 + lane];
            float4 h1 = g_h4[(size_t)en1.x * HID4 + lane];
            float4 h2 = g_h4[(size_t)en2.x * HID4 + lane];
            float4 h3 = g_h4[(size_t)en3.x * HID4 + lane];
            float w0 = __int_as_float(en0.y);
            float w1 = __int_as_float(en1.y);
            float w2 = __int_as_float(en2.y);
            float w3 = __int_as_float(en3.y);
            acc.x = fmaf(w0, h0.x, acc.x); acc.y = fmaf(w0, h0.y, acc.y);
            acc.z = fmaf(w0, h0.z, acc.z); acc.w = fmaf(w0, h0.w, acc.w);
            acc.x = fmaf(w1, h1.x, acc.x); acc.y = fmaf(w1, h1.y, acc.y);
            acc.z = fmaf(w1, h1.z, acc.z); acc.w = fmaf(w1, h1.w, acc.w);
            acc.x = fmaf(w2, h2.x, acc.x); acc.y = fmaf(w2, h2.y, acc.y);
            acc.z = fmaf(w2, h2.z, acc.z); acc.w = fmaf(w2, h2.w, acc.w);
            acc.x = fmaf(w3, h3.x, acc.x); acc.y = fmaf(w3, h3.y, acc.y);
            acc.z = fmaf(w3, h3.z, acc.z); acc.w = fmaf(w3, h3.w, acc.w);
        }
        for (; e < end; e++) {
            int2 en = g_entry[e];
            float w = __int_as_float(en.y);
            float4 hv = g_h4[(size_t)en.x * HID4 + lane];
            acc.x = fmaf(w, hv.x, acc.x);
            acc.y = fmaf(w, hv.y, acc.y);
            acc.z = fmaf(w, hv.z, acc.z);
            acc.w = fmaf(w, hv.w, acc.w);
        }
        *(float4*)(out + (size_t)c * HIDDEN + 4 * lane) = acc;

        ts.x += acc.x; ts.y += acc.y; ts.z += acc.z; ts.w += acc.w;
        tq.x = fmaf(acc.x, acc.x, tq.x);
        tq.y = fmaf(acc.y, acc.y, tq.y);
        tq.z = fmaf(acc.z, acc.z, tq.z);
        tq.w = fmaf(acc.w, acc.w, tq.w);
    }

    // Block reduction: 8 warps contend per column slot (shared double atomics).
    atomicAdd(&bsum[4 * lane + 0], (double)ts.x);
    atomicAdd(&bsum[4 * lane + 1], (double)ts.y);
    atomicAdd(&bsum[4 * lane + 2], (double)ts.z);
    atomicAdd(&bsum[4 * lane + 3], (double)ts.w);
    atomicAdd(&bsq[4 * lane + 0], (double)tq.x);
    atomicAdd(&bsq[4 * lane + 1], (double)tq.y);
    atomicAdd(&bsq[4 * lane + 2], (double)tq.z);
    atomicAdd(&bsq[4 * lane + 3], (double)tq.w);
    __syncthreads();

    if (tid < HIDDEN) {
        atomicAdd(&g_sum[tid], bsum[tid]);
        atomicAdd(&g_sumsq[tid], bsq[tid]);
    }
}

// ---------------------------------------------------------------------------
// BN: fold mean/var/gamma/beta into per-column affine (scale, shift).
// ---------------------------------------------------------------------------
__global__ void k_finalize(const float* __restrict__ gamma,
                           const float* __restrict__ beta)
{
    int c = threadIdx.x;                                 // 128 threads
    double mean = g_sum[c]   / (double)N_NODES;
    double var  = g_sumsq[c] / (double)N_NODES - mean * mean;
    float inv = rsqrtf((float)var + BN_EPS);
    float sc  = gamma[c] * inv;
    ((float*)g_scale4)[c] = sc;
    ((float*)g_shift4)[c] = beta[c] - sc * (float)mean;
}

// ---------------------------------------------------------------------------
// BN apply: out = out*scale + shift (vectorized float4).
// ---------------------------------------------------------------------------
__global__ void k_norm(float* __restrict__ out, int total)
{
    const int total4 = total >> 2;
    int i = blockIdx.x * blockDim.x + threadIdx.x;
    int stride = gridDim.x * blockDim.x;
    float4* o4 = (float4*)out;

    for (int idx = i; idx < total4; idx += stride) {
        int j = idx & (HID4 - 1);                        // column float4 group
        float4 v  = o4[idx];
        float4 sc = g_scale4[j];
        float4 sh = g_shift4[j];
        v.x = fmaf(v.x, sc.x, sh.x);
        v.y = fmaf(v.y, sc.y, sh.y);
        v.z = fmaf(v.z, sc.z, sh.z);
        v.w = fmaf(v.w, sc.w, sh.w);
        o4[idx] = v;
    }
}

// ---------------------------------------------------------------------------
extern "C" void kernel_launch(void* const* d_in, const int* in_sizes, int n_in,
                              void* d_out, int out_size)
{
    const float* x     = (const float*)d_in[0];
    const int*   ei    = (const int*)d_in[1];      // int32: JAX default config
    const float* W     = (const float*)d_in[2];
    // d_in[3] == b: cancels exactly inside BatchNorm -> unused
    const float* gamma = (const float*)d_in[4];
    const float* beta  = (const float*)d_in[5];
    float* out = (float*)d_out;

    const int E = in_sizes[1] / 2;

    k_init<<<512, 256>>>();
    k_deg<<<(E + 255) / 256, 256>>>(ei + E, E);          // col = edge_index[1]
    k_prep<<<(N_NODES + 255) / 256, 256>>>();
    k_fill<<<(E + 255) / 256, 256>>>(ei, E);
    k_gemm<<<(N_NODES + BLOCK_M - 1) / BLOCK_M, 256>>>(x, W);
    k_agg<<<2048, 256>>>(out);
    k_finalize<<<1, HIDDEN>>>(gamma, beta);
    k_norm<<<2048, 256>>>(out, out_size);
}

// round 15
// speedup vs baseline: 1.0440x; 1.0440x over previous
#include <cuda_runtime.h>

#define N_NODES 100000
#define N_EDGES 600000
#define HIDDEN  128
#define HID4    (HIDDEN / 4)
#define BN_EPS  1e-5f

typedef unsigned long long u64;

// Scratch (device globals: no allocation allowed in kernel_launch).
__device__ float4 g_h4[(size_t)N_NODES * HID4];    // relu(x) @ W
__device__ int    g_deg[N_NODES];
__device__ float  g_dinv[N_NODES];
__device__ int    g_off[N_NODES];                  // CSR segment starts (unordered)
__device__ int    g_cursor[N_NODES];               // fill cursors
__device__ int    g_total;                         // bump-allocator counter
__device__ int2   g_entry[N_EDGES];                // (src row, weight bits)
__device__ double g_sum[HIDDEN];
__device__ double g_sumsq[HIDDEN];
__device__ float4 g_scale4[HID4];
__device__ float4 g_shift4[HID4];

// Packed 2-lane fp32 FMA (sm_100+ PTX; ptxas never auto-emits FFMA2 from C++).
__device__ __forceinline__ u64 ffma2(u64 a, u64 b, u64 c)
{
    u64 d;
    asm("fma.rn.f32x2 %0, %1, %2, %3;" : "=l"(d) : "l"(a), "l"(b), "l"(c));
    return d;
}
__device__ __forceinline__ u64 dup2(float x)
{
    u64 d;
    asm("mov.b64 %0, {%1, %1};" : "=l"(d) : "f"(x));
    return d;
}

// ---------------------------------------------------------------------------
// Init: deg=1 (self loop), zero BN accumulators + bump counter. out needs NO
// zeroing: the gather-aggregation writes every row completely.
// ---------------------------------------------------------------------------
__global__ void k_init()
{
    int i = blockIdx.x * blockDim.x + threadIdx.x;
    int stride = gridDim.x * blockDim.x;
    for (int idx = i; idx < N_NODES; idx += stride) g_deg[idx] = 1;
    if (i < HIDDEN) { g_sum[i] = 0.0; g_sumsq[i] = 0.0; }
    if (i == 0) g_total = 0;
}

// ---------------------------------------------------------------------------
// Degree of target nodes (col), on top of the self-loop baseline of 1.
// edge_index is int32 (JAX default config downcasts int64 -> int32).
// ---------------------------------------------------------------------------
__global__ void k_deg(const int* __restrict__ col, int E)
{
    int i = blockIdx.x * blockDim.x + threadIdx.x;
    if (i < E) {
        int c = col[i];
        if ((unsigned)c < N_NODES) atomicAdd(&g_deg[c], 1);
    }
}

// ---------------------------------------------------------------------------
// Fused dinv + CSR segment allocation (no prefix scan needed: segments only
// have to be contiguous per node). Uniform-address atomicAdd is warp-
// aggregated by ptxas (REDUX.SUM + elect + one L2 atomic per warp).
// ---------------------------------------------------------------------------
__global__ void k_prep()
{
    int i = blockIdx.x * blockDim.x + threadIdx.x;
    if (i < N_NODES) {
        int dg = g_deg[i];
        g_dinv[i] = rsqrtf((float)dg);
        int pos = atomicAdd(&g_total, dg - 1);
        g_off[i]    = pos;
        g_cursor[i] = pos;
    }
}

// ---------------------------------------------------------------------------
// Fill CSR entries: per edge, (src row, dinv[r]*dinv[c]) bucketed by target.
// ---------------------------------------------------------------------------
__global__ void k_fill(const int* __restrict__ ei, int E)
{
    int i = blockIdx.x * blockDim.x + threadIdx.x;
    if (i < E) {
        int r = ei[i];
        int c = ei[E + i];
        if ((unsigned)c >= N_NODES) return;            // matches k_deg guard
        float w = 0.f;
        if ((unsigned)r < N_NODES) w = g_dinv[r] * g_dinv[c];
        else r = 0;                                    // defensive, w=0
        int pos = atomicAdd(&g_cursor[c], 1);
        g_entry[pos] = make_int2(r, __float_as_int(w));
    }
}

// ---------------------------------------------------------------------------
// h = relu(x) @ W.   Register-tiled SGEMM with packed f32x2 FMA.
// Block: 128 rows x 128 cols, 256 threads, 8x8 micro-tile per thread held as
// 32 packed f32x2 accumulators. Per k-step: 4 LDS.128 -> 32 FFMA2 (= 64 MACs).
// Launched at index 3 so the ncu capture (which empirically grabs launch #3)
// finally measures this kernel.
// ---------------------------------------------------------------------------
#define BLOCK_M 128
#define KC      32

__global__ void __launch_bounds__(256) k_gemm(const float* __restrict__ x,
                                              const float* __restrict__ W)
{
    __shared__ __align__(16) float Ws[KC][HIDDEN];     // 16 KB  [k][col]
    __shared__ __align__(16) float Xs[KC][BLOCK_M];    // 16 KB  [k][row]

    const int tid = threadIdx.x;
    const int tx  = tid & 15;            // col group: cols tx*8 .. tx*8+7
    const int ty  = tid >> 4;            // row group: rows ty*8 .. ty*8+7
    const int rowBase = blockIdx.x * BLOCK_M;

    u64 acc2[8][4];                      // [row][col-pair], packed f32x2
    #pragma unroll
    for (int r = 0; r < 8; r++)
        #pragma unroll
        for (int q = 0; q < 4; q++) acc2[r][q] = 0ull;

    for (int k0 = 0; k0 < HIDDEN; k0 += KC) {
        __syncthreads();                 // previous chunk fully consumed

        // W chunk: rows k0..k0+31 are 4096 contiguous floats. 4 float4/thread.
        {
            const float4* w4  = (const float4*)(W + k0 * HIDDEN);
            float4*       ws4 = (float4*)&Ws[0][0];
            #pragma unroll
            for (int i = 0; i < 4; i++)
                ws4[tid + 256 * i] = w4[tid + 256 * i];
        }
        // x chunk, transposed + ReLU -> Xs[k][row].
        {
            #pragma unroll
            for (int i = 0; i < 4; i++) {
                int f   = tid + 256 * i;
                int row = f >> 3;                   // 0..127
                int q   = f & 7;                    // float4 index within 32 cols
                int grow = rowBase + row;
                float4 v = make_float4(0.f, 0.f, 0.f, 0.f);
                if (grow < N_NODES) {
                    v = *(const float4*)(x + (size_t)grow * HIDDEN + k0 + 4 * q);
                    v.x = fmaxf(v.x, 0.f); v.y = fmaxf(v.y, 0.f);
                    v.z = fmaxf(v.z, 0.f); v.w = fmaxf(v.w, 0.f);
                }
                Xs[4 * q + 0][row] = v.x;
                Xs[4 * q + 1][row] = v.y;
                Xs[4 * q + 2][row] = v.z;
                Xs[4 * q + 3][row] = v.w;
            }
        }
        __syncthreads();

        #pragma unroll
        for (int kk = 0; kk < KC; kk++) {
            float  xr[8];
            float4 wq0, wq1;
            *(float4*)&xr[0] = *(const float4*)&Xs[kk][ty * 8];
            *(float4*)&xr[4] = *(const float4*)&Xs[kk][ty * 8 + 4];
            wq0 = *(const float4*)&Ws[kk][tx * 8];
            wq1 = *(const float4*)&Ws[kk][tx * 8 + 4];
            u64 w2[4];
            w2[0] = ((const u64*)&wq0)[0];
            w2[1] = ((const u64*)&wq0)[1];
            w2[2] = ((const u64*)&wq1)[0];
            w2[3] = ((const u64*)&wq1)[1];
            #pragma unroll
            for (int r = 0; r < 8; r++) {
                u64 x2 = dup2(xr[r]);
                #pragma unroll
                for (int q = 0; q < 4; q++)
                    acc2[r][q] = ffma2(x2, w2[q], acc2[r][q]);
            }
        }
    }

    // Epilogue: packed pairs are already column-ordered -> two STG.128/row.
    float* gh = (float*)g_h4;
    #pragma unroll
    for (int r = 0; r < 8; r++) {
        int row = rowBase + ty * 8 + r;
        if (row < N_NODES) {
            float* dst = gh + (size_t)row * HIDDEN + tx * 8;
            *(float4*)dst       = *(float4*)&acc2[r][0];
            *(float4*)(dst + 4) = *(float4*)&acc2[r][2];
        }
    }
}

// ---------------------------------------------------------------------------
// Gather aggregation + fused BN statistics. One warp per target node.
// out[c] = dinv[c]^2 * h[c] + sum_in-edges w * h[r];  full row in registers.
// R11-proven configuration: edge loop unrolled x2, 1024 blocks.
// Per-thread float partial sums -> block shared doubles -> global doubles.
// ---------------------------------------------------------------------------
__global__ void __launch_bounds__(256) k_agg(float* __restrict__ out)
{
    __shared__ double bsum[HIDDEN];
    __shared__ double bsq[HIDDEN];

    const int tid = threadIdx.x;
    if (tid < HIDDEN) { bsum[tid] = 0.0; bsq[tid] = 0.0; }
    __syncthreads();

    const int lane   = tid & 31;
    const int warp   = (blockIdx.x * blockDim.x + tid) >> 5;
    const int nwarps = (gridDim.x * blockDim.x) >> 5;

    float4 ts = make_float4(0.f, 0.f, 0.f, 0.f);     // per-thread col sums
    float4 tq = make_float4(0.f, 0.f, 0.f, 0.f);     // per-thread col sumsq

    for (int c = warp; c < N_NODES; c += nwarps) {
        float d = g_dinv[c];
        float wself = d * d;
        float4 v = g_h4[(size_t)c * HID4 + lane];
        float4 acc = make_float4(v.x * wself, v.y * wself, v.z * wself, v.w * wself);

        const int beg = g_off[c];
        const int end = beg + g_deg[c] - 1;
        int e = beg;
        for (; e + 2 <= end; e += 2) {
            int2 en0 = g_entry[e];
            int2 en1 = g_entry[e + 1];
            float4 h0 = g_h4[(size_t)en0.x * HID4 + lane];
            float4 h1 = g_h4[(size_t)en1.x * HID4 + lane];
            float w0 = __int_as_float(en0.y);
            float w1 = __int_as_float(en1.y);
            acc.x = fmaf(w0, h0.x, acc.x); acc.y = fmaf(w0, h0.y, acc.y);
            acc.z = fmaf(w0, h0.z, acc.z); acc.w = fmaf(w0, h0.w, acc.w);
            acc.x = fmaf(w1, h1.x, acc.x); acc.y = fmaf(w1, h1.y, acc.y);
            acc.z = fmaf(w1, h1.z, acc.z); acc.w = fmaf(w1, h1.w, acc.w);
        }
        if (e < end) {
            int2 en = g_entry[e];
            float w = __int_as_float(en.y);
            float4 hv = g_h4[(size_t)en.x * HID4 + lane];
            acc.x = fmaf(w, hv.x, acc.x);
            acc.y = fmaf(w, hv.y, acc.y);
            acc.z = fmaf(w, hv.z, acc.z);
            acc.w = fmaf(w, hv.w, acc.w);
        }
        *(float4*)(out + (size_t)c * HIDDEN + 4 * lane) = acc;

        ts.x += acc.x; ts.y += acc.y; ts.z += acc.z; ts.w += acc.w;
        tq.x = fmaf(acc.x, acc.x, tq.x);
        tq.y = fmaf(acc.y, acc.y, tq.y);
        tq.z = fmaf(acc.z, acc.z, tq.z);
        tq.w = fmaf(acc.w, acc.w, tq.w);
    }

    // Block reduction: 8 warps contend per column slot (shared double atomics).
    atomicAdd(&bsum[4 * lane + 0], (double)ts.x);
    atomicAdd(&bsum[4 * lane + 1], (double)ts.y);
    atomicAdd(&bsum[4 * lane + 2], (double)ts.z);
    atomicAdd(&bsum[4 * lane + 3], (double)ts.w);
    atomicAdd(&bsq[4 * lane + 0], (double)tq.x);
    atomicAdd(&bsq[4 * lane + 1], (double)tq.y);
    atomicAdd(&bsq[4 * lane + 2], (double)tq.z);
    atomicAdd(&bsq[4 * lane + 3], (double)tq.w);
    __syncthreads();

    if (tid < HIDDEN) {
        atomicAdd(&g_sum[tid], bsum[tid]);
        atomicAdd(&g_sumsq[tid], bsq[tid]);
    }
}

// ---------------------------------------------------------------------------
// BN: fold mean/var/gamma/beta into per-column affine (scale, shift).
// ---------------------------------------------------------------------------
__global__ void k_finalize(const float* __restrict__ gamma,
                           const float* __restrict__ beta)
{
    int c = threadIdx.x;                                 // 128 threads
    double mean = g_sum[c]   / (double)N_NODES;
    double var  = g_sumsq[c] / (double)N_NODES - mean * mean;
    float inv = rsqrtf((float)var + BN_EPS);
    float sc  = gamma[c] * inv;
    ((float*)g_scale4)[c] = sc;
    ((float*)g_shift4)[c] = beta[c] - sc * (float)mean;
}

// ---------------------------------------------------------------------------
// BN apply: out = out*scale + shift (vectorized float4).
// ---------------------------------------------------------------------------
__global__ void k_norm(float* __restrict__ out, int total)
{
    const int total4 = total >> 2;
    int i = blockIdx.x * blockDim.x + threadIdx.x;
    int stride = gridDim.x * blockDim.x;
    float4* o4 = (float4*)out;

    for (int idx = i; idx < total4; idx += stride) {
        int j = idx & (HID4 - 1);                        // column float4 group
        float4 v  = o4[idx];
        float4 sc = g_scale4[j];
        float4 sh = g_shift4[j];
        v.x = fmaf(v.x, sc.x, sh.x);
        v.y = fmaf(v.y, sc.y, sh.y);
        v.z = fmaf(v.z, sc.z, sh.z);
        v.w = fmaf(v.w, sc.w, sh.w);
        o4[idx] = v;
    }
}

// ---------------------------------------------------------------------------
extern "C" void kernel_launch(void* const* d_in, const int* in_sizes, int n_in,
                              void* d_out, int out_size)
{
    const float* x     = (const float*)d_in[0];
    const int*   ei    = (const int*)d_in[1];      // int32: JAX default config
    const float* W     = (const float*)d_in[2];
    // d_in[3] == b: cancels exactly inside BatchNorm -> unused
    const float* gamma = (const float*)d_in[4];
    const float* beta  = (const float*)d_in[5];
    float* out = (float*)d_out;

    const int E = in_sizes[1] / 2;

    k_init<<<512, 256>>>();                              // 0
    k_deg<<<(E + 255) / 256, 256>>>(ei + E, E);          // 1  col = edge_index[1]
    k_prep<<<(N_NODES + 255) / 256, 256>>>();            // 2
    k_gemm<<<(N_NODES + BLOCK_M - 1) / BLOCK_M, 256>>>(x, W);  // 3 <- profiled
    k_fill<<<(E + 255) / 256, 256>>>(ei, E);             // 4
    k_agg<<<1024, 256>>>(out);                           // 5
    k_finalize<<<1, HIDDEN>>>(gamma, beta);              // 6
    k_norm<<<2048, 256>>>(out, out_size);                // 7
}

// round 16
// speedup vs baseline: 1.0763x; 1.0309x over previous
#include <cuda_runtime.h>

#define N_NODES 100000
#define N_EDGES 600000
#define HIDDEN  128
#define HID4    (HIDDEN / 4)
#define BN_EPS  1e-5f

typedef unsigned long long u64;

// Scratch (device globals: no allocation allowed in kernel_launch).
__device__ float4 g_h4[(size_t)N_NODES * HID4];    // relu(x) @ W
__device__ int    g_deg[N_NODES];
__device__ float  g_dinv[N_NODES];
__device__ int    g_off[N_NODES];                  // CSR segment starts (unordered)
__device__ int    g_cursor[N_NODES];               // fill cursors
__device__ int    g_total;                         // bump-allocator counter
__device__ int2   g_entry[N_EDGES];                // (src row, weight bits)
__device__ double g_sum[HIDDEN];
__device__ double g_sumsq[HIDDEN];
__device__ float4 g_scale4[HID4];
__device__ float4 g_shift4[HID4];

// Packed 2-lane fp32 FMA (sm_100+ PTX; ptxas never auto-emits FFMA2 from C++).
__device__ __forceinline__ u64 ffma2(u64 a, u64 b, u64 c)
{
    u64 d;
    asm("fma.rn.f32x2 %0, %1, %2, %3;" : "=l"(d) : "l"(a), "l"(b), "l"(c));
    return d;
}
__device__ __forceinline__ u64 dup2(float x)
{
    u64 d;
    asm("mov.b64 %0, {%1, %1};" : "=l"(d) : "f"(x));
    return d;
}

// ---------------------------------------------------------------------------
// Init: deg=1 (self loop), zero BN accumulators + bump counter. out needs NO
// zeroing: the gather-aggregation writes every row completely.
// ---------------------------------------------------------------------------
__global__ void k_init()
{
    int i = blockIdx.x * blockDim.x + threadIdx.x;
    int stride = gridDim.x * blockDim.x;
    for (int idx = i; idx < N_NODES; idx += stride) g_deg[idx] = 1;
    if (i < HIDDEN) { g_sum[i] = 0.0; g_sumsq[i] = 0.0; }
    if (i == 0) g_total = 0;
}

// ---------------------------------------------------------------------------
// Degree of target nodes (col), on top of the self-loop baseline of 1.
// edge_index is int32 (JAX default config downcasts int64 -> int32).
// ---------------------------------------------------------------------------
__global__ void k_deg(const int* __restrict__ col, int E)
{
    int i = blockIdx.x * blockDim.x + threadIdx.x;
    if (i < E) {
        int c = col[i];
        if ((unsigned)c < N_NODES) atomicAdd(&g_deg[c], 1);
    }
}

// ---------------------------------------------------------------------------
// Fused dinv + CSR segment allocation (no prefix scan needed: segments only
// have to be contiguous per node). Uniform-address atomicAdd is warp-
// aggregated by ptxas (REDUX.SUM + elect + one L2 atomic per warp).
// ---------------------------------------------------------------------------
__global__ void k_prep()
{
    int i = blockIdx.x * blockDim.x + threadIdx.x;
    if (i < N_NODES) {
        int dg = g_deg[i];
        g_dinv[i] = rsqrtf((float)dg);
        int pos = atomicAdd(&g_total, dg - 1);
        g_off[i]    = pos;
        g_cursor[i] = pos;
    }
}

// ---------------------------------------------------------------------------
// Fill CSR entries: per edge, (src row, dinv[r]*dinv[c]) bucketed by target.
// ---------------------------------------------------------------------------
__global__ void k_fill(const int* __restrict__ ei, int E)
{
    int i = blockIdx.x * blockDim.x + threadIdx.x;
    if (i < E) {
        int r = ei[i];
        int c = ei[E + i];
        if ((unsigned)c >= N_NODES) return;            // matches k_deg guard
        float w = 0.f;
        if ((unsigned)r < N_NODES) w = g_dinv[r] * g_dinv[c];
        else r = 0;                                    // defensive, w=0
        int pos = atomicAdd(&g_cursor[c], 1);
        g_entry[pos] = make_int2(r, __float_as_int(w));
    }
}

// ---------------------------------------------------------------------------
// h = relu(x) @ W.   Register-tiled SGEMM with packed f32x2 FMA.
// Block: 128 rows x 128 cols, 256 threads, 8x8 micro-tile per thread held as
// 32 packed f32x2 accumulators. Per k-step: 4 LDS.128 -> 32 FFMA2 (= 64 MACs).
// __launch_bounds__(256, 2): force <=128 regs so 2 CTAs (16 warps) co-reside
// per SM -- R15 measured 134 regs -> 1 CTA -> occ 12.3%, issue 29% (latency
// starved). This tests the FFMA2 issue-rate with adequate warp parallelism.
// ---------------------------------------------------------------------------
#define BLOCK_M 128
#define KC      32

__global__ void __launch_bounds__(256, 2) k_gemm(const float* __restrict__ x,
                                                 const float* __restrict__ W)
{
    __shared__ __align__(16) float Ws[KC][HIDDEN];     // 16 KB  [k][col]
    __shared__ __align__(16) float Xs[KC][BLOCK_M];    // 16 KB  [k][row]

    const int tid = threadIdx.x;
    const int tx  = tid & 15;            // col group: cols tx*8 .. tx*8+7
    const int ty  = tid >> 4;            // row group: rows ty*8 .. ty*8+7
    const int rowBase = blockIdx.x * BLOCK_M;

    u64 acc2[8][4];                      // [row][col-pair], packed f32x2
    #pragma unroll
    for (int r = 0; r < 8; r++)
        #pragma unroll
        for (int q = 0; q < 4; q++) acc2[r][q] = 0ull;

    for (int k0 = 0; k0 < HIDDEN; k0 += KC) {
        __syncthreads();                 // previous chunk fully consumed

        // W chunk: rows k0..k0+31 are 4096 contiguous floats. 4 float4/thread.
        {
            const float4* w4  = (const float4*)(W + k0 * HIDDEN);
            float4*       ws4 = (float4*)&Ws[0][0];
            #pragma unroll
            for (int i = 0; i < 4; i++)
                ws4[tid + 256 * i] = w4[tid + 256 * i];
        }
        // x chunk, transposed + ReLU -> Xs[k][row].
        {
            #pragma unroll
            for (int i = 0; i < 4; i++) {
                int f   = tid + 256 * i;
                int row = f >> 3;                   // 0..127
                int q   = f & 7;                    // float4 index within 32 cols
                int grow = rowBase + row;
                float4 v = make_float4(0.f, 0.f, 0.f, 0.f);
                if (grow < N_NODES) {
                    v = *(const float4*)(x + (size_t)grow * HIDDEN + k0 + 4 * q);
                    v.x = fmaxf(v.x, 0.f); v.y = fmaxf(v.y, 0.f);
                    v.z = fmaxf(v.z, 0.f); v.w = fmaxf(v.w, 0.f);
                }
                Xs[4 * q + 0][row] = v.x;
                Xs[4 * q + 1][row] = v.y;
                Xs[4 * q + 2][row] = v.z;
                Xs[4 * q + 3][row] = v.w;
            }
        }
        __syncthreads();

        #pragma unroll
        for (int kk = 0; kk < KC; kk++) {
            float  xr[8];
            float4 wq0, wq1;
            *(float4*)&xr[0] = *(const float4*)&Xs[kk][ty * 8];
            *(float4*)&xr[4] = *(const float4*)&Xs[kk][ty * 8 + 4];
            wq0 = *(const float4*)&Ws[kk][tx * 8];
            wq1 = *(const float4*)&Ws[kk][tx * 8 + 4];
            u64 w2[4];
            w2[0] = ((const u64*)&wq0)[0];
            w2[1] = ((const u64*)&wq0)[1];
            w2[2] = ((const u64*)&wq1)[0];
            w2[3] = ((const u64*)&wq1)[1];
            #pragma unroll
            for (int r = 0; r < 8; r++) {
                u64 x2 = dup2(xr[r]);
                #pragma unroll
                for (int q = 0; q < 4; q++)
                    acc2[r][q] = ffma2(x2, w2[q], acc2[r][q]);
            }
        }
    }

    // Epilogue: packed pairs are already column-ordered -> two STG.128/row.
    float* gh = (float*)g_h4;
    #pragma unroll
    for (int r = 0; r < 8; r++) {
        int row = rowBase + ty * 8 + r;
        if (row < N_NODES) {
            float* dst = gh + (size_t)row * HIDDEN + tx * 8;
            *(float4*)dst       = *(float4*)&acc2[r][0];
            *(float4*)(dst + 4) = *(float4*)&acc2[r][2];
        }
    }
}

// ---------------------------------------------------------------------------
// Gather aggregation + fused BN statistics. One warp per target node.
// out[c] = dinv[c]^2 * h[c] + sum_in-edges w * h[r];  full row in registers.
// R11-proven configuration: edge loop unrolled x2, 1024 blocks.
// Per-thread float partial sums -> block shared doubles -> global doubles.
// ---------------------------------------------------------------------------
__global__ void __launch_bounds__(256) k_agg(float* __restrict__ out)
{
    __shared__ double bsum[HIDDEN];
    __shared__ double bsq[HIDDEN];

    const int tid = threadIdx.x;
    if (tid < HIDDEN) { bsum[tid] = 0.0; bsq[tid] = 0.0; }
    __syncthreads();

    const int lane   = tid & 31;
    const int warp   = (blockIdx.x * blockDim.x + tid) >> 5;
    const int nwarps = (gridDim.x * blockDim.x) >> 5;

    float4 ts = make_float4(0.f, 0.f, 0.f, 0.f);     // per-thread col sums
    float4 tq = make_float4(0.f, 0.f, 0.f, 0.f);     // per-thread col sumsq

    for (int c = warp; c < N_NODES; c += nwarps) {
        float d = g_dinv[c];
        float wself = d * d;
        float4 v = g_h4[(size_t)c * HID4 + lane];
        float4 acc = make_float4(v.x * wself, v.y * wself, v.z * wself, v.w * wself);

        const int beg = g_off[c];
        const int end = beg + g_deg[c] - 1;
        int e = beg;
        for (; e + 2 <= end; e += 2) {
            int2 en0 = g_entry[e];
            int2 en1 = g_entry[e + 1];
            float4 h0 = g_h4[(size_t)en0.x * HID4 + lane];
            float4 h1 = g_h4[(size_t)en1.x * HID4 + lane];
            float w0 = __int_as_float(en0.y);
            float w1 = __int_as_float(en1.y);
            acc.x = fmaf(w0, h0.x, acc.x); acc.y = fmaf(w0, h0.y, acc.y);
            acc.z = fmaf(w0, h0.z, acc.z); acc.w = fmaf(w0, h0.w, acc.w);
            acc.x = fmaf(w1, h1.x, acc.x); acc.y = fmaf(w1, h1.y, acc.y);
            acc.z = fmaf(w1, h1.z, acc.z); acc.w = fmaf(w1, h1.w, acc.w);
        }
        if (e < end) {
            int2 en = g_entry[e];
            float w = __int_as_float(en.y);
            float4 hv = g_h4[(size_t)en.x * HID4 + lane];
            acc.x = fmaf(w, hv.x, acc.x);
            acc.y = fmaf(w, hv.y, acc.y);
            acc.z = fmaf(w, hv.z, acc.z);
            acc.w = fmaf(w, hv.w, acc.w);
        }
        *(float4*)(out + (size_t)c * HIDDEN + 4 * lane) = acc;

        ts.x += acc.x; ts.y += acc.y; ts.z += acc.z; ts.w += acc.w;
        tq.x = fmaf(acc.x, acc.x, tq.x);
        tq.y = fmaf(acc.y, acc.y, tq.y);
        tq.z = fmaf(acc.z, acc.z, tq.z);
        tq.w = fmaf(acc.w, acc.w, tq.w);
    }

    // Block reduction: 8 warps contend per column slot (shared double atomics).
    atomicAdd(&bsum[4 * lane + 0], (double)ts.x);
    atomicAdd(&bsum[4 * lane + 1], (double)ts.y);
    atomicAdd(&bsum[4 * lane + 2], (double)ts.z);
    atomicAdd(&bsum[4 * lane + 3], (double)ts.w);
    atomicAdd(&bsq[4 * lane + 0], (double)tq.x);
    atomicAdd(&bsq[4 * lane + 1], (double)tq.y);
    atomicAdd(&bsq[4 * lane + 2], (double)tq.z);
    atomicAdd(&bsq[4 * lane + 3], (double)tq.w);
    __syncthreads();

    if (tid < HIDDEN) {
        atomicAdd(&g_sum[tid], bsum[tid]);
        atomicAdd(&g_sumsq[tid], bsq[tid]);
    }
}

// ---------------------------------------------------------------------------
// BN: fold mean/var/gamma/beta into per-column affine (scale, shift).
// ---------------------------------------------------------------------------
__global__ void k_finalize(const float* __restrict__ gamma,
                           const float* __restrict__ beta)
{
    int c = threadIdx.x;                                 // 128 threads
    double mean = g_sum[c]   / (double)N_NODES;
    double var  = g_sumsq[c] / (double)N_NODES - mean * mean;
    float inv = rsqrtf((float)var + BN_EPS);
    float sc  = gamma[c] * inv;
    ((float*)g_scale4)[c] = sc;
    ((float*)g_shift4)[c] = beta[c] - sc * (float)mean;
}

// ---------------------------------------------------------------------------
// BN apply: out = out*scale + shift (vectorized float4).
// ---------------------------------------------------------------------------
__global__ void k_norm(float* __restrict__ out, int total)
{
    const int total4 = total >> 2;
    int i = blockIdx.x * blockDim.x + threadIdx.x;
    int stride = gridDim.x * blockDim.x;
    float4* o4 = (float4*)out;

    for (int idx = i; idx < total4; idx += stride) {
        int j = idx & (HID4 - 1);                        // column float4 group
        float4 v  = o4[idx];
        float4 sc = g_scale4[j];
        float4 sh = g_shift4[j];
        v.x = fmaf(v.x, sc.x, sh.x);
        v.y = fmaf(v.y, sc.y, sh.y);
        v.z = fmaf(v.z, sc.z, sh.z);
        v.w = fmaf(v.w, sc.w, sh.w);
        o4[idx] = v;
    }
}

// ---------------------------------------------------------------------------
extern "C" void kernel_launch(void* const* d_in, const int* in_sizes, int n_in,
                              void* d_out, int out_size)
{
    const float* x     = (const float*)d_in[0];
    const int*   ei    = (const int*)d_in[1];      // int32: JAX default config
    const float* W     = (const float*)d_in[2];
    // d_in[3] == b: cancels exactly inside BatchNorm -> unused
    const float* gamma = (const float*)d_in[4];
    const float* beta  = (const float*)d_in[5];
    float* out = (float*)d_out;

    const int E = in_sizes[1] / 2;

    k_init<<<512, 256>>>();                              // 0
    k_deg<<<(E + 255) / 256, 256>>>(ei + E, E);          // 1  col = edge_index[1]
    k_prep<<<(N_NODES + 255) / 256, 256>>>();            // 2
    k_gemm<<<(N_NODES + BLOCK_M - 1) / BLOCK_M, 256>>>(x, W);  // 3 <- profiled
    k_fill<<<(E + 255) / 256, 256>>>(ei, E);             // 4
    k_agg<<<1024, 256>>>(out);                           // 5
    k_finalize<<<1, HIDDEN>>>(gamma, beta);              // 6
    k_norm<<<2048, 256>>>(out, out_size);                // 7
}